// round 1
// baseline (speedup 1.0000x reference)
#include <cuda_runtime.h>
#include <math_constants.h>

// Problem constants
#define BB 4
#define NN 4096
#define F_IN 64
#define N_PROP 64
#define N_DIM 4
#define N_FILT 128
#define KN 39          // neighbors kept (top-40 minus self)

// Scratch (allocation-free rule: __device__ globals)
__device__ float g_features[BB*NN*N_PROP];
__device__ float g_coords[BB*NN*N_DIM];
__device__ int   g_nbr_idx[BB*NN*KN];
__device__ float g_nbr_w[BB*NN*KN];

// ---------------------------------------------------------------------------
// K1: features = x@W_flr + b_flr ; coords = x@W_s + b_s
// 256 threads, 4 rows per block. x row in smem, W read from L1 (16KB, cached).
// ---------------------------------------------------------------------------
__global__ void k_feat(const float* __restrict__ x,
                       const float* __restrict__ Wf, const float* __restrict__ bf,
                       const float* __restrict__ Ws, const float* __restrict__ bs)
{
    __shared__ float xs[4][F_IN];
    int rr  = threadIdx.x >> 6;     // 0..3 row within block
    int j   = threadIdx.x & 63;     // output feature
    int row = blockIdx.x * 4 + rr;

    xs[rr][j] = x[row * F_IN + j];
    __syncthreads();

    float acc = bf[j];
#pragma unroll 16
    for (int i = 0; i < F_IN; i++)
        acc = fmaf(xs[rr][i], Wf[i * N_PROP + j], acc);
    g_features[row * N_PROP + j] = acc;

    if (j < N_DIM) {
        float c = bs[j];
#pragma unroll 16
        for (int i = 0; i < F_IN; i++)
            c = fmaf(xs[rr][i], Ws[i * N_DIM + j], c);
        g_coords[row * N_DIM + j] = c;
    }
}

// ---------------------------------------------------------------------------
// K2: per-query exact top-39 nearest (excluding self) in 4-D coord space.
// All 4096 coords of the batch live in smem (64KB, dynamic). Thread = query.
// Unsorted 39-entry buffer + threshold insert + rescan for new max.
// Lockstep j loop -> smem candidate read is a broadcast (conflict-free).
// ---------------------------------------------------------------------------
extern __shared__ float4 sc[];

__global__ void k_knn()
{
    int b = blockIdx.y;
    const float4* cp = (const float4*)(g_coords + b * NN * N_DIM);
    for (int i = threadIdx.x; i < NN; i += blockDim.x) sc[i] = cp[i];
    __syncthreads();

    int n = blockIdx.x * blockDim.x + threadIdx.x;   // query index in batch
    float4 q = sc[n];

    float bd[KN];
    int   bi[KN];
#pragma unroll
    for (int k = 0; k < KN; k++) { bd[k] = CUDART_INF_F; bi[k] = 0; }
    float worst = CUDART_INF_F;
    int   wp = 0;

    for (int j = 0; j < NN; j++) {
        float4 p = sc[j];
        float dx = q.x - p.x, dy = q.y - p.y, dz = q.z - p.z, dw = q.w - p.w;
        float d = fmaf(dx, dx, fmaf(dy, dy, fmaf(dz, dz, dw * dw)));
        if (d < worst && j != n) {
            bd[wp] = d; bi[wp] = j;
            // rescan for new worst
            worst = bd[0]; wp = 0;
#pragma unroll
            for (int k = 1; k < KN; k++)
                if (bd[k] > worst) { worst = bd[k]; wp = k; }
        }
    }

    int base = (b * NN + n) * KN;
#pragma unroll 4
    for (int k = 0; k < KN; k++) {
        g_nbr_idx[base + k] = bi[k];
        g_nbr_w[base + k]   = expf(-10.0f * bd[k]);   // dist >= 0, abs is no-op
    }
}

// ---------------------------------------------------------------------------
// K3: weighted gather -> max/mean over 39 neighbors -> concat(x, max, mean)
//     -> @ W_out + b_out. Warp per query; 8 warps/block.
//     Lane owns 2 feature channels during aggregation, 4 output cols in GEMM.
// ---------------------------------------------------------------------------
__global__ void k_agg(const float* __restrict__ x,
                      const float* __restrict__ Wo, const float* __restrict__ bo,
                      float* __restrict__ out)
{
    __shared__ float upd[8][192];
    int warp = threadIdx.x >> 5, lane = threadIdx.x & 31;
    int r = blockIdx.x * 8 + warp;                 // global row 0..B*N-1
    const float* fb = g_features + (r >> 12) * NN * N_PROP;  // batch base
    int base = r * KN;

    float mx0 = -CUDART_INF_F, mx1 = -CUDART_INF_F, s0 = 0.f, s1 = 0.f;
#pragma unroll 3
    for (int k = 0; k < KN; k++) {
        int   j = __ldg(&g_nbr_idx[base + k]);     // uniform across warp
        float w = __ldg(&g_nbr_w[base + k]);
        float2 f = ((const float2*)(fb + j * N_PROP))[lane];
        float v0 = w * f.x, v1 = w * f.y;
        mx0 = fmaxf(mx0, v0); mx1 = fmaxf(mx1, v1);
        s0 += v0; s1 += v1;
    }
    const float inv = 1.0f / 39.0f;

    float2 xv = ((const float2*)(x + r * F_IN))[lane];
    upd[warp][2 * lane]           = xv.x;
    upd[warp][2 * lane + 1]       = xv.y;
    upd[warp][64  + 2 * lane]     = mx0;
    upd[warp][64  + 2 * lane + 1] = mx1;
    upd[warp][128 + 2 * lane]     = s0 * inv;
    upd[warp][128 + 2 * lane + 1] = s1 * inv;
    __syncwarp();

    float4 acc = ((const float4*)bo)[lane];
#pragma unroll 8
    for (int c = 0; c < 192; c++) {
        float u = upd[warp][c];                          // smem broadcast
        float4 wv = ((const float4*)(Wo + c * N_FILT))[lane];  // coalesced, L1-hot
        acc.x = fmaf(u, wv.x, acc.x);
        acc.y = fmaf(u, wv.y, acc.y);
        acc.z = fmaf(u, wv.z, acc.z);
        acc.w = fmaf(u, wv.w, acc.w);
    }
    ((float4*)(out + r * N_FILT))[lane] = acc;
}

// ---------------------------------------------------------------------------
extern "C" void kernel_launch(void* const* d_in, const int* in_sizes, int n_in,
                              void* d_out, int out_size)
{
    const float* x  = (const float*)d_in[0];
    const float* Wf = (const float*)d_in[1];
    const float* bf = (const float*)d_in[2];
    const float* Ws = (const float*)d_in[3];
    const float* bs = (const float*)d_in[4];
    const float* Wo = (const float*)d_in[5];
    const float* bo = (const float*)d_in[6];
    float* out = (float*)d_out;

    // 64KB dynamic smem for the per-batch coord table (idempotent, capture-safe)
    cudaFuncSetAttribute(k_knn, cudaFuncAttributeMaxDynamicSharedMemorySize, 65536);

    k_feat<<<BB * NN / 4, 256>>>(x, Wf, bf, Ws, bs);

    dim3 g2(NN / 128, BB);
    k_knn<<<g2, 128, 65536>>>();

    k_agg<<<BB * NN / 8, 256>>>(x, Wo, bo, out);
}

// round 2
// speedup vs baseline: 2.5218x; 2.5218x over previous
#include <cuda_runtime.h>
#include <math_constants.h>

// Problem constants
#define BB 4
#define NN 4096
#define F_IN 64
#define N_PROP 64
#define N_DIM 4
#define N_FILT 128
#define KN 39          // neighbors kept (top-40 minus self)
#define FULL 0xFFFFFFFFu

// Scratch (allocation-free rule: __device__ globals)
__device__ float g_features[BB*NN*N_PROP];
__device__ float g_coords[BB*NN*N_DIM];
__device__ int   g_nbr_idx[BB*NN*KN];
__device__ float g_nbr_w[BB*NN*KN];

// ---------------------------------------------------------------------------
// K1: features = x@W_flr + b_flr ; coords = x@W_s + b_s  (unchanged)
// ---------------------------------------------------------------------------
__global__ void k_feat(const float* __restrict__ x,
                       const float* __restrict__ Wf, const float* __restrict__ bf,
                       const float* __restrict__ Ws, const float* __restrict__ bs)
{
    __shared__ float xs[4][F_IN];
    int rr  = threadIdx.x >> 6;
    int j   = threadIdx.x & 63;
    int row = blockIdx.x * 4 + rr;

    xs[rr][j] = x[row * F_IN + j];
    __syncthreads();

    float acc = bf[j];
#pragma unroll 16
    for (int i = 0; i < F_IN; i++)
        acc = fmaf(xs[rr][i], Wf[i * N_PROP + j], acc);
    g_features[row * N_PROP + j] = acc;

    if (j < N_DIM) {
        float c = bs[j];
#pragma unroll 16
        for (int i = 0; i < F_IN; i++)
            c = fmaf(xs[rr][i], Ws[i * N_DIM + j], c);
        g_coords[row * N_DIM + j] = c;
    }
}

// ---------------------------------------------------------------------------
// K2: warp-per-query exact top-39 via 2-level radix select + boundary sort.
// Block = 8 warps = 8 queries. Coords of the whole batch in smem (64KB).
// smem layout: float4 sc[4096] | uint hist[8][1024] | uint2 bbuf[8][48] | uint cnts[8][2]
// ---------------------------------------------------------------------------
#define NBBUF 48

__device__ __forceinline__ float dist4(float4 q, float4 p) {
    float dx = q.x - p.x, dy = q.y - p.y, dz = q.z - p.z, dw = q.w - p.w;
    return fmaf(dx, dx, fmaf(dy, dy, fmaf(dz, dz, dw * dw)));
}

__global__ void __launch_bounds__(256, 2) k_knn()
{
    extern __shared__ char smem_raw[];
    float4* sc   = (float4*)smem_raw;                              // 65536
    uint*   hist = (uint*)(smem_raw + 65536);                      // 32768
    uint2*  bbuf = (uint2*)(smem_raw + 65536 + 32768);             // 3072
    uint*   cnts = (uint*)(smem_raw + 65536 + 32768 + 3072);       // 64

    int b = blockIdx.y;
    const float4* cp = (const float4*)(g_coords + b * NN * N_DIM);
    for (int i = threadIdx.x; i < NN; i += blockDim.x) sc[i] = cp[i];
    __syncthreads();

    int w    = threadIdx.x >> 5;
    int lane = threadIdx.x & 31;
    int n    = blockIdx.x * 8 + w;          // query index within batch
    float4 q = sc[n];
    uint* h  = hist + w * 1024;

    // ---------------- Pass A: 10-bit digit (bits 30..21) ----------------
#pragma unroll 8
    for (int k = 0; k < 32; k++) h[lane * 32 + k] = 0;
    __syncwarp();

#pragma unroll 4
    for (int t = 0; t < 128; t++) {
        int j = lane + 32 * t;
        uint key = __float_as_uint(dist4(q, sc[j]));
        if (j != n) atomicAdd(&h[key >> 21], 1);
    }
    __syncwarp();

    int local = 0;
#pragma unroll 8
    for (int k = 0; k < 32; k++) local += h[lane * 32 + k];
    int incl = local;
#pragma unroll
    for (int o = 1; o < 32; o <<= 1) {
        int v = __shfl_up_sync(FULL, incl, o);
        if (lane >= o) incl += v;
    }
    int excl = incl - local;

    unsigned ball = __ballot_sync(FULL, excl < KN && KN <= incl);
    int sel = __ffs(ball) - 1;
    int t0 = 0, kin = 0;
    if (lane == sel) {
        int c = excl;
#pragma unroll 8
        for (int k = 0; k < 32; k++) {
            int hc = h[lane * 32 + k];
            if (c + hc >= KN && kin == 0) { t0 = lane * 32 + k; kin = KN - c; }
            c += hc;
        }
    }
    t0  = __shfl_sync(FULL, t0, sel);
    kin = __shfl_sync(FULL, kin, sel);

    // ---------------- Pass B: next 8 bits (bits 20..13) within bin t0 ----------------
#pragma unroll
    for (int k = 0; k < 8; k++) h[lane * 8 + k] = 0;
    __syncwarp();

#pragma unroll 4
    for (int t = 0; t < 128; t++) {
        int j = lane + 32 * t;
        uint key = __float_as_uint(dist4(q, sc[j]));
        if (j != n && (int)(key >> 21) == t0) atomicAdd(&h[(key >> 13) & 0xFF], 1);
    }
    __syncwarp();

    local = 0;
#pragma unroll
    for (int k = 0; k < 8; k++) local += h[lane * 8 + k];
    incl = local;
#pragma unroll
    for (int o = 1; o < 32; o <<= 1) {
        int v = __shfl_up_sync(FULL, incl, o);
        if (lane >= o) incl += v;
    }
    excl = incl - local;

    ball = __ballot_sync(FULL, excl < kin && kin <= incl);
    sel = __ffs(ball) - 1;
    int t1 = 0, kin2 = 0;
    if (lane == sel) {
        int c = excl;
#pragma unroll
        for (int k = 0; k < 8; k++) {
            int hc = h[lane * 8 + k];
            if (c + hc >= kin && kin2 == 0) { t1 = lane * 8 + k; kin2 = kin - c; }
            c += hc;
        }
    }
    t1 = __shfl_sync(FULL, t1, sel);

    uint P18 = ((uint)t0 << 8) | (uint)t1;   // 18-bit prefix of the 39th key

    // ---------------- Collect ----------------
    if (lane == 0) { cnts[w * 2] = 0; cnts[w * 2 + 1] = 0; }
    __syncwarp();

    int base = (b * NN + n) * KN;
#pragma unroll 2
    for (int t = 0; t < 128; t++) {
        int j = lane + 32 * t;
        float d = dist4(q, sc[j]);
        uint key = __float_as_uint(d);
        uint p = key >> 13;
        if (j != n) {
            if (p < P18) {
                uint pos = atomicAdd(&cnts[w * 2], 1);
                g_nbr_idx[base + pos] = j;
                g_nbr_w[base + pos]   = expf(-10.0f * d);
            } else if (p == P18) {
                uint bp = atomicAdd(&cnts[w * 2 + 1], 1);
                if (bp < NBBUF) bbuf[w * NBBUF + bp] = make_uint2(key, (uint)j);
            }
        }
    }
    __syncwarp();

    int cless = cnts[w * 2];
    int need  = KN - cless;                 // >=1 by construction
    int M     = min((int)cnts[w * 2 + 1], NBBUF);

    // exact rank among boundary candidates (full key, idx tiebreak)
    for (int s = lane; s < M; s += 32) {
        uint2 e = bbuf[w * NBBUF + s];
        int rank = 0;
        for (int i = 0; i < M; i++) {
            uint2 o = bbuf[w * NBBUF + i];
            rank += (o.x < e.x) || (o.x == e.x && o.y < e.y);
        }
        if (rank < need) {
            uint pos = atomicAdd(&cnts[w * 2], 1);
            g_nbr_idx[base + pos] = (int)e.y;
            g_nbr_w[base + pos]   = expf(-10.0f * __uint_as_float(e.x));
        }
    }
}

// ---------------------------------------------------------------------------
// K3: weighted gather -> max/mean -> concat -> @W_out + b_out  (unchanged)
// ---------------------------------------------------------------------------
__global__ void k_agg(const float* __restrict__ x,
                      const float* __restrict__ Wo, const float* __restrict__ bo,
                      float* __restrict__ out)
{
    __shared__ float upd[8][192];
    int warp = threadIdx.x >> 5, lane = threadIdx.x & 31;
    int r = blockIdx.x * 8 + warp;
    const float* fb = g_features + (r >> 12) * NN * N_PROP;
    int base = r * KN;

    float mx0 = -CUDART_INF_F, mx1 = -CUDART_INF_F, s0 = 0.f, s1 = 0.f;
#pragma unroll 3
    for (int k = 0; k < KN; k++) {
        int   j = __ldg(&g_nbr_idx[base + k]);
        float w = __ldg(&g_nbr_w[base + k]);
        float2 f = ((const float2*)(fb + j * N_PROP))[lane];
        float v0 = w * f.x, v1 = w * f.y;
        mx0 = fmaxf(mx0, v0); mx1 = fmaxf(mx1, v1);
        s0 += v0; s1 += v1;
    }
    const float inv = 1.0f / 39.0f;

    float2 xv = ((const float2*)(x + r * F_IN))[lane];
    upd[warp][2 * lane]           = xv.x;
    upd[warp][2 * lane + 1]       = xv.y;
    upd[warp][64  + 2 * lane]     = mx0;
    upd[warp][64  + 2 * lane + 1] = mx1;
    upd[warp][128 + 2 * lane]     = s0 * inv;
    upd[warp][128 + 2 * lane + 1] = s1 * inv;
    __syncwarp();

    float4 acc = ((const float4*)bo)[lane];
#pragma unroll 8
    for (int c = 0; c < 192; c++) {
        float u = upd[warp][c];
        float4 wv = ((const float4*)(Wo + c * N_FILT))[lane];
        acc.x = fmaf(u, wv.x, acc.x);
        acc.y = fmaf(u, wv.y, acc.y);
        acc.z = fmaf(u, wv.z, acc.z);
        acc.w = fmaf(u, wv.w, acc.w);
    }
    ((float4*)(out + r * N_FILT))[lane] = acc;
}

// ---------------------------------------------------------------------------
extern "C" void kernel_launch(void* const* d_in, const int* in_sizes, int n_in,
                              void* d_out, int out_size)
{
    const float* x  = (const float*)d_in[0];
    const float* Wf = (const float*)d_in[1];
    const float* bf = (const float*)d_in[2];
    const float* Ws = (const float*)d_in[3];
    const float* bs = (const float*)d_in[4];
    const float* Wo = (const float*)d_in[5];
    const float* bo = (const float*)d_in[6];
    float* out = (float*)d_out;

    const int knn_smem = 65536 + 32768 + 3072 + 64;   // 101440
    cudaFuncSetAttribute(k_knn, cudaFuncAttributeMaxDynamicSharedMemorySize, knn_smem);

    k_feat<<<BB * NN / 4, 256>>>(x, Wf, bf, Ws, bs);

    dim3 g2(NN / 8, BB);
    k_knn<<<g2, 256, knn_smem>>>();

    k_agg<<<BB * NN / 8, 256>>>(x, Wo, bo, out);
}